// round 15
// baseline (speedup 1.0000x reference)
#include <cuda_runtime.h>

static constexpr int B = 256;
static constexpr int S = 2048;
static constexpr int T = 48;

typedef unsigned long long u64;

// cross-kernel scratch (static __device__: allowed, no dynamic alloc)
__device__ float g_dir[B][2][48];     // [batch][0=alpha_1023 dir, 1=beta_1024 dir]
__device__ float g_c[B][6];           // per-chain log-scales (seg 0..5)
__device__ float g_numpart[B * 6];    // per-chain numerator partials

// ---- packed f32x2 helpers (Blackwell FFMA2: only reachable via PTX) ----
__device__ __forceinline__ u64 pack2(float x, float y) {
    u64 r; asm("mov.b64 %0, {%1, %2};" : "=l"(r) : "f"(x), "f"(y)); return r;
}
__device__ __forceinline__ void unpack2(u64 v, float& x, float& y) {
    asm("mov.b64 {%0, %1}, %2;" : "=f"(x), "=f"(y) : "l"(v));
}
__device__ __forceinline__ u64 ffma2(u64 a, u64 b, u64 c) {
    u64 d; asm("fma.rn.f32x2 %0, %1, %2, %3;" : "=l"(d) : "l"(a), "l"(b), "l"(c)); return d;
}
__device__ __forceinline__ u64 fadd2(u64 a, u64 b) {
    u64 d; asm("add.rn.f32x2 %0, %1, %2;" : "=l"(d) : "l"(a), "l"(b)); return d;
}

// One scaled-exp-domain semiring chain, transposed pair packing (R7/R13 body).
// BW=0: alpha forward (matvec then *exp(e)); BW=1: beta backward (*exp(e)
// then matvec). Lane l owns states (2l,2l+1); lanes 24..31 padding (E pairs
// zero -> state identically 0; buf slots never read).
// niter/reset_i/ep RUNTIME -> ONE inlined instance per BW (R5 lesson).
// reset_i >= 0: lane0-normalize there, zero scale (PF stitch; reset%8==7!).
// Prefetch is UNGUARDED: all 8-step lookaheads verified in-bounds for the
// segment offsets used below.
template<int BW>
__device__ __forceinline__ void run_chain(
    const float* __restrict__ ep,    // adjusted emission base (+ j0)
    const u64 (&EA)[24], const u64 (&EB)[24],
    float px, float py, int niter, int reset_i, int lane,
    float2 (*buf)[32],               // per-warp double buffer [2][32]
    float& pxOut, float& pyOut, float& cOut)
{
    int cexp = 0;                    // accumulated power-of-two scale
    float2 ebuf[8];
    int cb = 0;

#define E_OFF(i) ( BW ? (size_t)(S - 1 - (i)) * T : (size_t)((i) + 1) * T )

#pragma unroll
    for (int u = 0; u < 8; ++u)
        ebuf[u] = *(const float2*)(ep + E_OFF(u));

#define BODY(i, u, RENORM) do {                                            \
    float2 e = ebuf[u];                                                    \
    ebuf[u] = *(const float2*)(ep + E_OFF((i) + 8));  /* always in-bounds */\
    float fex = __expf(e.x);                                               \
    float fey = __expf(e.y);                                               \
    float sx = BW ? px * fex : px;                                         \
    float sy = BW ? py * fey : py;                                         \
    buf[cb][lane] = make_float2(sx, sy);                                   \
    __syncwarp();                                                          \
    u64 a0=0ull,a1=0ull,a2=0ull,a3=0ull,a4=0ull,a5=0ull,a6=0ull,a7=0ull;   \
    const float4* bv = (const float4*)buf[cb];                             \
    _Pragma("unroll")                                                      \
    for (int m = 0; m < 12; m += 4) {                                      \
        float4 v0 = bv[m];                                                 \
        u64 b0 = pack2(v0.x, v0.y), b1 = pack2(v0.z, v0.w);                \
        a0 = ffma2(EA[2*m  ], b0, a0);  a4 = ffma2(EB[2*m  ], b0, a4);     \
        a1 = ffma2(EA[2*m+1], b1, a1);  a5 = ffma2(EB[2*m+1], b1, a5);     \
        float4 v1 = bv[m+1];                                               \
        u64 b2 = pack2(v1.x, v1.y), b3 = pack2(v1.z, v1.w);                \
        a2 = ffma2(EA[2*m+2], b2, a2);  a6 = ffma2(EB[2*m+2], b2, a6);     \
        a3 = ffma2(EA[2*m+3], b3, a3);  a7 = ffma2(EB[2*m+3], b3, a7);     \
        float4 v2 = bv[m+2];                                               \
        u64 b4 = pack2(v2.x, v2.y), b5 = pack2(v2.z, v2.w);                \
        a0 = ffma2(EA[2*m+4], b4, a0);  a4 = ffma2(EB[2*m+4], b4, a4);     \
        a1 = ffma2(EA[2*m+5], b5, a1);  a5 = ffma2(EB[2*m+5], b5, a5);     \
        float4 v3 = bv[m+3];                                               \
        u64 b6 = pack2(v3.x, v3.y), b7 = pack2(v3.z, v3.w);                \
        a2 = ffma2(EA[2*m+6], b6, a2);  a6 = ffma2(EB[2*m+6], b6, a6);     \
        a3 = ffma2(EA[2*m+7], b7, a3);  a7 = ffma2(EB[2*m+7], b7, a7);     \
    }                                                                      \
    u64 q0 = fadd2(fadd2(a0, a1), fadd2(a2, a3));                          \
    u64 q1 = fadd2(fadd2(a4, a5), fadd2(a6, a7));                          \
    float x0, y0; unpack2(q0, x0, y0);                                     \
    float x1, y1; unpack2(q1, x1, y1);                                     \
    float n0 = x0 + y0, n1 = x1 + y1;                                      \
    px = BW ? n0 : n0 * fex;                                               \
    py = BW ? n1 : n1 * fey;                                               \
    cb ^= 1;                                                               \
    if (RENORM) {                                                          \
        float ref = __shfl_sync(0xffffffffu, px, 0);                       \
        if ((i) == reset_i) {                                              \
            float inv = __fdividef(1.f, ref);                              \
            px *= inv; py *= inv;                                          \
            cexp = 0;                       /* stitch boundary: discard */ \
        } else {                                                           \
            int ex = (__float_as_int(ref) >> 23) & 255;                    \
            float sc = __int_as_float((254 - ex) << 23); /* 2^(127-ex) */  \
            px *= sc; py *= sc;                                            \
            cexp += ex - 127;                                              \
        }                                                                  \
    }                                                                      \
} while (0)

    int nmain = niter & ~7;
    for (int i = 0; i < nmain; i += 8) {
#pragma unroll
        for (int u = 0; u < 8; ++u) BODY(i + u, u, (u == 7));
    }
#pragma unroll
    for (int u = 0; u < 8; ++u)
        if (nmain + u < niter) BODY(nmain + u, u, false);

    // final exact renorm (lane0-normalize) + exact log of scale
    float c = (float)cexp * 0.69314718055994531f;
    {
        float ref = __shfl_sync(0xffffffffu, px, 0);
        float inv = __fdividef(1.f, ref);
        px *= inv; py *= inv;
        c += __logf(ref);
    }
    pxOut = px; pyOut = py; cOut = c;
#undef BODY
#undef E_OFF
}

// Kernel 1: 296 blocks (=2x148: every SM hosts exactly 2 resident blocks via
// the bid%148 placement LUT) x 192 threads. Trailing blocks carry fewer
// ACTIVE warps so no SM exceeds 11 active chain-warps (vs 12/6 imbalance of
// the 256-block layout): blocks 0..147 -> 6 chains, 148..203 -> 5,
// 204..295 -> 4 (total 1536). Idle warps exit immediately; NO __syncthreads.
// Chain C -> batch C/6, seg C%6 (seg 0..2 fw, 3..5 bw).
// Schedule (R13-validated stitch, burn-in 24, reset i=23):
//  fw s0 exact t=1..357 (357);  s1 ep0+333T n357 r23;  s2 ep0+666T n357 r23 -> alpha dir
//  bw s0 exact e=2047..1690 (358); s1 ep0-334T n357 r23; s2 ep0-667T n357 r23 -> beta dir
// Epilogue per warp: numerator partial over s in [seg*2048/6,(seg+1)*2048/6).
__global__ void __launch_bounds__(192, 2)
crf_chains(const float* __restrict__ emis,
           const int*   __restrict__ tagsw,   // int32 view; int64 auto-detected
           const int*   __restrict__ mask,
           const float* __restrict__ trans,
           const float* __restrict__ startT,
           const float* __restrict__ endT)
{
    __shared__ __align__(16) float2 bufs[6][2][32];  // [warp][double-buf][lane]

    const int blk = blockIdx.x;
    const int tid = threadIdx.x;
    const int w   = tid >> 5;
    const int l   = tid & 31;

    int base, count;
    if (blk < 148)      { base = 6 * blk;              count = 6; }
    else if (blk < 204) { base = 888  + 5 * (blk-148); count = 5; }
    else                { base = 1168 + 4 * (blk-204); count = 4; }
    if (w >= count) return;                  // idle warp: free the slot

    const int C   = base + w;                // global chain id
    const int b   = C / 6;
    const int seg = C % 6;
    const bool fw = (seg < 3);
    const int  si = fw ? seg : seg - 3;

    const bool act = l < 24;
    const int j0 = act ? 2*l     : 0;
    const int j1 = act ? 2*l + 1 : 0;

    // per-lane exp(transition) pair constants (96 regs), transposed packing
    u64 EA[24], EB[24];
    if (fw) {
#pragma unroll
        for (int k = 0; k < 24; ++k) {
            float a0 = __expf(trans[(2*k)*T   + j0]);
            float a1 = __expf(trans[(2*k+1)*T + j0]);
            float b0 = __expf(trans[(2*k)*T   + j1]);
            float b1 = __expf(trans[(2*k+1)*T + j1]);
            EA[k] = act ? pack2(a0, a1) : 0ull;
            EB[k] = act ? pack2(b0, b1) : 0ull;
        }
    } else {
#pragma unroll
        for (int k = 0; k < 24; ++k) {
            float a0 = __expf(trans[j0*T + 2*k]);
            float a1 = __expf(trans[j0*T + 2*k+1]);
            float b0 = __expf(trans[j1*T + 2*k]);
            float b1 = __expf(trans[j1*T + 2*k+1]);
            EA[k] = act ? pack2(a0, a1) : 0ull;
            EB[k] = act ? pack2(b0, b1) : 0ull;
        }
    }

    const size_t bbase = (size_t)b * S * T;
    const float* ep0 = emis + bbase + j0;

    const int niter = (!fw && si == 0) ? 358 : 357;
    const int reset = (si == 0) ? -1 : 23;
    const float* ep = fw
        ? ep0 + (size_t)(si == 0 ? 0 : si == 1 ? 333 : 666) * T
        : ep0 - (size_t)(si == 0 ? 0 : si == 1 ? 334 : 667) * T;

    float p0x, p0y;
    if (si != 0) {
        p0x = act ? 1.f : 0.f; p0y = p0x;                     // uniform burn-in
    } else if (fw) {
        float2 e0 = *(const float2*)(ep0);                    // t = 0
        p0x = act ? __expf(startT[j0] + e0.x) : 0.f;
        p0y = act ? __expf(startT[j1] + e0.y) : 0.f;
    } else {
        p0x = act ? __expf(endT[j0]) : 0.f;
        p0y = act ? __expf(endT[j1]) : 0.f;
    }

    float pfx, pfy, cfin;
    if (fw) run_chain<0>(ep, EA, EB, p0x, p0y, niter, reset, l, bufs[w], pfx, pfy, cfin);
    else    run_chain<1>(ep, EA, EB, p0x, p0y, niter, reset, l, bufs[w], pfx, pfy, cfin);

    if (act) {
        if (seg == 2) { g_dir[b][0][2*l] = pfx; g_dir[b][0][2*l+1] = pfy; }
        if (seg == 5) { g_dir[b][1][2*l] = pfx; g_dir[b][1][2*l+1] = pfy; }
    }
    if (l == 0) g_c[b][seg] = cfin;

    // ---- per-warp numerator partial over s in [s0, s1) ----
    const size_t tbase = (size_t)b * S;
    const int s0 = (seg * S) / 6;
    const int s1 = ((seg + 1) * S) / 6;

    // tags dtype detection: int64 iff sampled odd 32-bit words all zero
    int oddw = tagsw[2 * (tbase + s0 + l) + 1];
    const bool is64 = !__any_sync(0xffffffffu, oddw != 0);

    float num = 0.f;
    for (int s = s0 + l; s < s1; s += 32) {
        int cur = is64 ? tagsw[(tbase + s) * 2] : tagsw[tbase + s];
        if (s == 0) {
            num += startT[cur] + emis[bbase + cur];
        } else {
            int prev = is64 ? tagsw[(tbase + s - 1) * 2] : tagsw[tbase + s - 1];
            float m = (float)mask[tbase + s];
            num += (trans[prev*T + cur] + emis[bbase + (size_t)s*T + cur]) * m;
        }
        if (s == S - 1) num += endT[cur];
    }
#pragma unroll
    for (int d = 16; d; d >>= 1) num += __shfl_xor_sync(0xffffffffu, num, d);
    if (l == 0) g_numpart[C] = num;
}

// Kernel 2: tiny combine. grid B x 64 thr.
__global__ void __launch_bounds__(64)
crf_combine(float* __restrict__ out)
{
    __shared__ float shRed[64];
    const int b   = blockIdx.x;
    const int tid = threadIdx.x;

    shRed[tid] = (tid < 48) ? g_dir[b][0][tid] * g_dir[b][1][tid] : 0.f;
    __syncthreads();

    if (tid == 0) {
        float dot = 0.f;
#pragma unroll
        for (int k = 0; k < 48; ++k) dot += shRed[k];
        float cs = 0.f, nm = 0.f;
#pragma unroll
        for (int k = 0; k < 6; ++k) { cs += g_c[b][k]; nm += g_numpart[6*b + k]; }
        out[b] = __logf(dot) + cs - nm;              // NLL
    }
}

extern "C" void kernel_launch(void* const* d_in, const int* in_sizes, int n_in,
                              void* d_out, int out_size) {
    (void)in_sizes; (void)n_in; (void)out_size;
    const float* emis   = (const float*)d_in[0];
    const int*   tagsw  = (const int*)  d_in[1];
    const int*   mask   = (const int*)  d_in[2];
    const float* trans  = (const float*)d_in[3];
    const float* startT = (const float*)d_in[4];
    const float* endT   = (const float*)d_in[5];
    crf_chains <<<296, 192>>>(emis, tagsw, mask, trans, startT, endT);
    crf_combine<<<B, 64>>>((float*)d_out);
}

// round 17
// speedup vs baseline: 1.9518x; 1.9518x over previous
#include <cuda_runtime.h>
#include <cuda_bf16.h>
#include <cstdint>

static constexpr int B = 256;
static constexpr int S = 2048;
static constexpr int T = 48;
static constexpr int NSTEP = 80;   // uniform iterations per segment-row

// cross-kernel scratch (static __device__: allowed, no dynamic alloc)
__device__ float g_dir[B][2][48];  // [batch][0=fw alpha_1023, 1=bw beta_1023]
__device__ float g_cc[B][2][16];   // per-row log-scales
__device__ float g_num[B][2];      // numerator halves

// pack two fp32 -> bf16x2 (lo = first arg). Same helper used for BOTH A and B
// fragments, so the hi/lo convention is self-consistent inside the MMA.
__device__ __forceinline__ uint32_t bf2(float lo, float hi) {
    uint32_t r;
    asm("cvt.rn.bf16x2.f32 %0, %1, %2;" : "=r"(r) : "f"(hi), "f"(lo));
    return r;
}

// D += A(16x8,bf16) x B(8x8,bf16), fp32 accumulate (warp-collective)
__device__ __forceinline__ void mma8(float* d, uint32_t a0, uint32_t a1, uint32_t b0) {
    asm volatile(
        "mma.sync.aligned.m16n8k8.row.col.f32.bf16.bf16.f32 "
        "{%0,%1,%2,%3}, {%4,%5}, {%6}, {%0,%1,%2,%3};"
        : "+f"(d[0]), "+f"(d[1]), "+f"(d[2]), "+f"(d[3])
        : "r"(a0), "r"(a1), "r"(b0));
}

// Segment schedule (PF split, 16 rows per direction per batch).
// fw: trusted 80 + 13x64 + 56 + 55 = 1023 -> alpha_1023; resets 15/23/24.
// bw: trusted 80 + 13x64 + 56 + 56 = 1024 -> beta_1023;  resets 15/23/23.
// All resets lie in the renorm set {7,15,23,24,31,...}.
__device__ __forceinline__ void seg_params(int r, int bwd, int& t0, int& rs) {
    if (!bwd) {
        if (r == 0)       { t0 = 1;                rs = -1; }
        else if (r <= 13) { t0 = 64 * r + 1;       rs = 15; }
        else if (r == 14) { t0 = 889;              rs = 23; }
        else              { t0 = 944;              rs = 24; }
    } else {
        if (r == 0)       { t0 = 2047;             rs = -1; }
        else if (r <= 13) { t0 = 1983 - 64*(r-1);  rs = 15; }
        else if (r == 14) { t0 = 1159;             rs = 23; }
        else              { t0 = 1103;             rs = 23; }
    }
}

// 16 scaled-exp-domain chains per warp as rows of iterated m16n8k8 GEMMs.
// BW=0 (fw): C' = (cvt(C) x E) .* F ;  BW=1 (bw): C' = cvt(C .* F) x E^T.
// m16n8k8 C-fragment mapping == A-fragment mapping, so cvt is in-place.
// Per-row renorm every 8 steps (+ extra at i==24) via quad-shfl of col0;
// per-row reset at its PF stitch boundary (reset uniform within each quad).
template<int BW>
__device__ __forceinline__ void run_gemm_chain(
    const float* __restrict__ emis, int b,
    const uint32_t (&E)[36],          // B fragments, E[kt*6+nt]
    float (&cc)[24],                  // C fragments (state), cc[nt*4+q]
    int t0_lo, int t0_hi, int reset_lo, int reset_hi,
    int lane, float (&c_out)[2])
{
    const int c2 = (lane & 3) * 2;
    const int qb = lane & ~3;         // quad base lane (holds col0 of the row)
    int cexp_lo = 0, cexp_hi = 0;
    const long long dT = BW ? -(long long)T : (long long)T;
    const float* pl = emis + ((size_t)b * S + t0_lo) * T + c2;
    const float* ph = emis + ((size_t)b * S + t0_hi) * T + c2;

    float2 eb[2][12];                 // 2-step-deep emission prefetch
#pragma unroll
    for (int s = 0; s < 2; ++s) {
#pragma unroll
        for (int nt = 0; nt < 6; ++nt) {
            eb[s][nt]     = *(const float2*)(pl + 8 * nt);
            eb[s][6 + nt] = *(const float2*)(ph + 8 * nt);
        }
        pl += dT; ph += dT;
    }

    for (int ii = 0; ii < NSTEP; ii += 8) {
#pragma unroll
        for (int u = 0; u < 8; ++u) {
            const int i = ii + u;
            // exps of this step's emissions (independent of state)
            float F[24];
#pragma unroll
            for (int nt = 0; nt < 6; ++nt) {
                float2 lo = eb[u & 1][nt], hi = eb[u & 1][6 + nt];
                F[nt*4+0] = __expf(lo.x); F[nt*4+1] = __expf(lo.y);
                F[nt*4+2] = __expf(hi.x); F[nt*4+3] = __expf(hi.y);
            }
            // prefetch step i+2 (verified in-bounds for all segment bases)
#pragma unroll
            for (int nt = 0; nt < 6; ++nt) {
                eb[u & 1][nt]     = *(const float2*)(pl + 8 * nt);
                eb[u & 1][6 + nt] = *(const float2*)(ph + 8 * nt);
            }
            pl += dT; ph += dT;

            // A fragments (C layout == A layout for m16n8k8)
            uint32_t a0[6], a1[6];
#pragma unroll
            for (int kt = 0; kt < 6; ++kt) {
                if (BW) {
                    a0[kt] = bf2(cc[kt*4+0]*F[kt*4+0], cc[kt*4+1]*F[kt*4+1]);
                    a1[kt] = bf2(cc[kt*4+2]*F[kt*4+2], cc[kt*4+3]*F[kt*4+3]);
                } else {
                    a0[kt] = bf2(cc[kt*4+0], cc[kt*4+1]);
                    a1[kt] = bf2(cc[kt*4+2], cc[kt*4+3]);
                }
            }
            // C = A x E  (6 n-tiles x 6 k-tiles)
#pragma unroll
            for (int nt = 0; nt < 6; ++nt) {
                float d[4] = {0.f, 0.f, 0.f, 0.f};
#pragma unroll
                for (int kt = 0; kt < 6; ++kt)
                    mma8(d, a0[kt], a1[kt], E[kt*6 + nt]);
                if (BW) {
                    cc[nt*4+0] = d[0]; cc[nt*4+1] = d[1];
                    cc[nt*4+2] = d[2]; cc[nt*4+3] = d[3];
                } else {
                    cc[nt*4+0] = d[0]*F[nt*4+0]; cc[nt*4+1] = d[1]*F[nt*4+1];
                    cc[nt*4+2] = d[2]*F[nt*4+2]; cc[nt*4+3] = d[3]*F[nt*4+3];
                }
            }

            // renorm every 8 steps, plus the extra stitch step i==24
            if (u == 7 || (u == 0 && ii == 24)) {
                float ref_lo = __shfl_sync(0xffffffffu, cc[0], qb);
                float ref_hi = __shfl_sync(0xffffffffu, cc[2], qb);
                float sl, sh;
                if (i == reset_lo) {                 // stitch: exact, discard
                    sl = __fdividef(1.f, ref_lo); cexp_lo = 0;
                } else {
                    int ex = (__float_as_int(ref_lo) >> 23) & 255;
                    sl = __int_as_float((254 - ex) << 23); cexp_lo += ex - 127;
                }
                if (i == reset_hi) {
                    sh = __fdividef(1.f, ref_hi); cexp_hi = 0;
                } else {
                    int ex = (__float_as_int(ref_hi) >> 23) & 255;
                    sh = __int_as_float((254 - ex) << 23); cexp_hi += ex - 127;
                }
#pragma unroll
                for (int nt = 0; nt < 6; ++nt) {
                    cc[nt*4+0] *= sl; cc[nt*4+1] *= sl;
                    cc[nt*4+2] *= sh; cc[nt*4+3] *= sh;
                }
            }
        }
    }

    // final exact renorm per row + log of scale
    float ref_lo = __shfl_sync(0xffffffffu, cc[0], qb);
    float ref_hi = __shfl_sync(0xffffffffu, cc[2], qb);
    float il = __fdividef(1.f, ref_lo);
    float ih = __fdividef(1.f, ref_hi);
#pragma unroll
    for (int nt = 0; nt < 6; ++nt) {
        cc[nt*4+0] *= il; cc[nt*4+1] *= il;
        cc[nt*4+2] *= ih; cc[nt*4+3] *= ih;
    }
    const float LN2 = 0.69314718055994531f;
    c_out[0] = (float)cexp_lo * LN2 + __logf(ref_lo);
    c_out[1] = (float)cexp_hi * LN2 + __logf(ref_hi);
}

// Kernel 1: 128 blocks x 128 thr. Warp W = blk*4+w: W<256 -> fw batch W,
// else bw batch W-256. No smem, no __syncthreads; warps fully independent.
__global__ void __launch_bounds__(128)
crf_chains(const float* __restrict__ emis,
           const int*   __restrict__ tagsw,   // int32 view; int64 auto-detected
           const int*   __restrict__ mask,
           const float* __restrict__ trans,
           const float* __restrict__ startT,
           const float* __restrict__ endT)
{
    const int tid  = threadIdx.x;
    const int w    = tid >> 5;
    const int lane = tid & 31;
    const int W    = blockIdx.x * 4 + w;
    const int bwd  = (W >= 256) ? 1 : 0;
    const int b    = bwd ? W - 256 : W;
    const int g    = lane >> 2;
    const int c2   = (lane & 3) * 2;

    // E fragments in bf16 (36 regs). fw: B = E (k=from, n=to); bw: B = E^T.
    uint32_t E[36];
    if (!bwd) {
#pragma unroll
        for (int kt = 0; kt < 6; ++kt)
#pragma unroll
            for (int nt = 0; nt < 6; ++nt)
                E[kt*6+nt] = bf2(__expf(trans[(8*kt + c2    ) * T + 8*nt + g]),
                                 __expf(trans[(8*kt + c2 + 1) * T + 8*nt + g]));
    } else {
#pragma unroll
        for (int kt = 0; kt < 6; ++kt)
#pragma unroll
            for (int nt = 0; nt < 6; ++nt)
                E[kt*6+nt] = bf2(__expf(trans[(8*nt + g) * T + 8*kt + c2    ]),
                                 __expf(trans[(8*nt + g) * T + 8*kt + c2 + 1]));
    }

    // initial state: row 0 = exact init; rows 1..15 = uniform burn-in start
    float cc[24];
    const size_t bbase = (size_t)b * S * T;
#pragma unroll
    for (int nt = 0; nt < 6; ++nt) {
        int col = 8*nt + c2;
        if (g == 0) {
            if (!bwd) {
                cc[nt*4+0] = __expf(startT[col]     + emis[bbase + col]);
                cc[nt*4+1] = __expf(startT[col + 1] + emis[bbase + col + 1]);
            } else {
                cc[nt*4+0] = __expf(endT[col]);
                cc[nt*4+1] = __expf(endT[col + 1]);
            }
        } else {
            cc[nt*4+0] = 1.f; cc[nt*4+1] = 1.f;
        }
        cc[nt*4+2] = 1.f; cc[nt*4+3] = 1.f;   // rows 8..15 all burn-in
    }

    int t0l, rsl, t0h, rsh;
    seg_params(g,     bwd, t0l, rsl);
    seg_params(g + 8, bwd, t0h, rsh);

    float cO[2];
    if (!bwd) run_gemm_chain<0>(emis, b, E, cc, t0l, t0h, rsl, rsh, lane, cO);
    else      run_gemm_chain<1>(emis, b, E, cc, t0l, t0h, rsl, rsh, lane, cO);

    if ((lane & 3) == 0) {
        g_cc[b][bwd][g]     = cO[0];
        g_cc[b][bwd][g + 8] = cO[1];
    }
    if (g == 7) {                      // row 15 = final direction vector
#pragma unroll
        for (int nt = 0; nt < 6; ++nt) {
            g_dir[b][bwd][8*nt + c2]     = cc[nt*4+2];
            g_dir[b][bwd][8*nt + c2 + 1] = cc[nt*4+3];
        }
    }

    // ---- tags dtype detection: probe FIRST 64 words only (in-bounds for
    // both int32 and int64 buffers). int64 iff odd words all zero.
    int oddw = tagsw[2 * lane + 1];
    const bool is64 = !__any_sync(0xffffffffu, oddw != 0);

    // ---- numerator partial: fw warp s in [0,1024), bw warp [1024,2048) ----
    const size_t tbase = (size_t)b * S;
    const int s0 = bwd ? 1024 : 0;
    float num = 0.f;
#pragma unroll 4
    for (int k = 0; k < 32; ++k) {
        int s = s0 + lane + 32 * k;
        int cur = is64 ? tagsw[(tbase + s) * 2] : tagsw[tbase + s];
        if (s == 0) {
            num += startT[cur] + emis[bbase + cur];
        } else {
            int prev = is64 ? tagsw[(tbase + s - 1) * 2] : tagsw[tbase + s - 1];
            float m = (float)mask[tbase + s];
            num += (trans[prev * T + cur] + emis[bbase + (size_t)s * T + cur]) * m;
        }
        if (s == S - 1) num += endT[cur];
    }
#pragma unroll
    for (int d = 16; d; d >>= 1) num += __shfl_xor_sync(0xffffffffu, num, d);
    if (lane == 0) g_num[b][bwd] = num;
}

// Kernel 2: tiny combine. grid B x 64 thr.
__global__ void __launch_bounds__(64)
crf_combine(float* __restrict__ out)
{
    __shared__ float shRed[64];
    const int b   = blockIdx.x;
    const int tid = threadIdx.x;

    shRed[tid] = (tid < 48) ? g_dir[b][0][tid] * g_dir[b][1][tid] : 0.f;
    __syncthreads();

    if (tid == 0) {
        float dot = 0.f;
#pragma unroll
        for (int k = 0; k < 48; ++k) dot += shRed[k];
        float cs = 0.f;
#pragma unroll
        for (int r = 0; r < 16; ++r) cs += g_cc[b][0][r] + g_cc[b][1][r];
        out[b] = __logf(dot) + cs - g_num[b][0] - g_num[b][1];   // NLL
    }
}

extern "C" void kernel_launch(void* const* d_in, const int* in_sizes, int n_in,
                              void* d_out, int out_size) {
    (void)in_sizes; (void)n_in; (void)out_size;
    const float* emis   = (const float*)d_in[0];
    const int*   tagsw  = (const int*)  d_in[1];
    const int*   mask   = (const int*)  d_in[2];
    const float* trans  = (const float*)d_in[3];
    const float* startT = (const float*)d_in[4];
    const float* endT   = (const float*)d_in[5];
    crf_chains <<<128, 128>>>(emis, tagsw, mask, trans, startT, endT);
    crf_combine<<<B, 64>>>((float*)d_out);
}